// round 15
// baseline (speedup 1.0000x reference)
#include <cuda_runtime.h>
#include <cuda_bf16.h>
#include <cuda_fp16.h>
#include <cstdint>

// Problem constants
#define Bc 4
#define Tc 2048
#define Fc 512
#define Hc 8
#define DKc 64
#define Mdim (Bc*Tc)   // 8192
#define Ndim Fc        // 512
#define Kdim Fc        // 512

#define LOG2E 1.44269504088896340736f

// ---- fp16 mma m16n8k16, fp32 accumulate ----
__device__ __forceinline__ void mma_f16(float* c,
                                        uint32_t a0, uint32_t a1, uint32_t a2, uint32_t a3,
                                        uint32_t b0, uint32_t b1) {
    asm volatile("mma.sync.aligned.m16n8k16.row.col.f32.f16.f16.f32 "
                 "{%0,%1,%2,%3}, {%4,%5,%6,%7}, {%8,%9}, {%0,%1,%2,%3};"
                 : "+f"(c[0]), "+f"(c[1]), "+f"(c[2]), "+f"(c[3])
                 : "r"(a0), "r"(a1), "r"(a2), "r"(a3), "r"(b0), "r"(b1));
}
__device__ __forceinline__ uint32_t smem_u32(const void* p) {
    return (uint32_t)__cvta_generic_to_shared(p);
}
__device__ __forceinline__ void cp_async16(uint32_t dst, const void* src) {
    asm volatile("cp.async.cg.shared.global [%0], [%1], 16;" :: "r"(dst), "l"(src));
}
__device__ __forceinline__ void cp_commit() {
    asm volatile("cp.async.commit_group;");
}
__device__ __forceinline__ void ldm_x4(uint32_t& r0, uint32_t& r1, uint32_t& r2, uint32_t& r3,
                                       uint32_t addr) {
    asm volatile("ldmatrix.sync.aligned.m8n8.x4.shared.b16 {%0,%1,%2,%3}, [%4];"
                 : "=r"(r0), "=r"(r1), "=r"(r2), "=r"(r3) : "r"(addr));
}
__device__ __forceinline__ void ldm_x4t(uint32_t& r0, uint32_t& r1, uint32_t& r2, uint32_t& r3,
                                        uint32_t addr) {
    asm volatile("ldmatrix.sync.aligned.m8n8.x4.trans.shared.b16 {%0,%1,%2,%3}, [%4];"
                 : "=r"(r0), "=r"(r1), "=r"(r2), "=r"(r3) : "r"(addr));
}
__device__ __forceinline__ void ldm_x2t(uint32_t& r0, uint32_t& r1, uint32_t addr) {
    asm volatile("ldmatrix.sync.aligned.m8n8.x2.trans.shared.b16 {%0,%1}, [%2];"
                 : "=r"(r0), "=r"(r1) : "r"(addr));
}
__device__ __forceinline__ void ldm_x2(uint32_t& r0, uint32_t& r1, uint32_t addr) {
    asm volatile("ldmatrix.sync.aligned.m8n8.x2.shared.b16 {%0,%1}, [%2];"
                 : "=r"(r0), "=r"(r1) : "r"(addr));
}
__device__ __forceinline__ float ex2(float x) {
    float y; asm("ex2.approx.f32 %0, %1;" : "=f"(y) : "f"(x)); return y;
}
// ---- packed f16x2 ops ----
__device__ __forceinline__ uint32_t cvt_h2(float lo, float hi) {
    uint32_t d; asm("cvt.rn.f16x2.f32 %0, %1, %2;" : "=r"(d) : "f"(hi), "f"(lo)); return d;
}
__device__ __forceinline__ uint32_t add_h2u(uint32_t a, uint32_t b) {
    uint32_t d; asm("add.f16x2 %0, %1, %2;" : "=r"(d) : "r"(a), "r"(b)); return d;
}
__device__ __forceinline__ uint32_t sub_h2u(uint32_t a, uint32_t b) {
    uint32_t d; asm("sub.f16x2 %0, %1, %2;" : "=r"(d) : "r"(a), "r"(b)); return d;
}
__device__ __forceinline__ uint32_t max_h2u(uint32_t a, uint32_t b) {
    uint32_t d; asm("max.f16x2 %0, %1, %2;" : "=r"(d) : "r"(a), "r"(b)); return d;
}
__device__ __forceinline__ uint32_t prmtu(uint32_t a, uint32_t b, uint32_t c) {
    uint32_t d; asm("prmt.b32 %0, %1, %2, %3;" : "=r"(d) : "r"(a), "r"(b), "r"(c)); return d;
}
__device__ __forceinline__ uint32_t ex2_h2u(uint32_t a) {
    uint32_t d; asm("ex2.approx.f16x2 %0, %1;" : "=r"(d) : "r"(a)); return d;
}

// Scratch
__device__ __half g_Xh[3][(size_t)Mdim*Fc];   // [0]=query; [1]/[2]=key/value COMPACTED
__device__ __half g_Wh[4][(size_t)Fc*Fc];
__device__ __half g_Qh[(size_t)Bc*Hc*Tc*DKc];
__device__ __half g_Kh[(size_t)Bc*Hc*Tc*DKc];   // compacted per (b,h)
__device__ __half g_Vh[(size_t)Bc*Hc*Tc*DKc];   // compacted
__device__ __half g_CTXh[(size_t)Mdim*Fc];
__device__ __half g_MBh[(size_t)Bc*Tc];         // compacted bias: 0 (j<nv) / -inf
__device__ int    g_RK[(size_t)Bc*Tc];          // rank among valid, -1 if masked
__device__ int    g_NV[Bc];                     // valid-key count per batch

// ---------------------------------------------------------------------------
// fp32 -> fp16 convert; jobs 1,2 (key,value) gather rows to rank position.
// ---------------------------------------------------------------------------
struct CvtJobs7 { const float* src[7]; __half* dst[7]; int nblk[7]; };

__global__ __launch_bounds__(256)
void cvt_kernel(CvtJobs7 J, const int* __restrict__ rank)
{
    const int j = blockIdx.y;
    if ((int)blockIdx.x >= J.nblk[j]) return;
    const float* s = J.src[j];
    __half* d = J.dst[j];
    const size_t i = ((size_t)blockIdx.x * 256 + threadIdx.x) * 4;

    size_t o = i;
    if (j == 1 || j == 2) {              // key/value: gather to compacted row
        const int row = (int)(i >> 9);   // Fc = 512 floats per row
        const int b = row >> 11, t = row & 2047;
        const int r = rank[b * Tc + t];
        if (r < 0) return;               // masked row: drop (dst rows >= nv stay 0)
        o = (((size_t)(b << 11) + r) << 9) + (i & 511);
    }
    float4 v = *(const float4*)(s + i);
    __half2 h0 = __float22half2_rn(make_float2(v.x, v.y));
    __half2 h1 = __float22half2_rn(make_float2(v.z, v.w));
    uint2 w; w.x = *(uint32_t*)&h0; w.y = *(uint32_t*)&h1;
    *(uint2*)(d + o) = w;
}

// ---------------------------------------------------------------------------
// Mask compaction: rank (stable prefix), nv count, compacted fp16 bias.
// ---------------------------------------------------------------------------
__global__ __launch_bounds__(256)
void compact_mask_kernel(const int* __restrict__ m, int* __restrict__ rank,
                         __half* __restrict__ mbc, int* __restrict__ nv)
{
    const int b = blockIdx.x;
    const int tid = threadIdx.x;
    const int lane = tid & 31, wid = tid >> 5;
    const int* mb_ = m + b * Tc;

    int loc[8], s = 0;
    #pragma unroll
    for (int j = 0; j < 8; j++) { loc[j] = mb_[tid*8 + j] ? 1 : 0; s += loc[j]; }

    int inc = s;
    #pragma unroll
    for (int off = 1; off < 32; off <<= 1) {
        int v = __shfl_up_sync(0xffffffffu, inc, off);
        if (lane >= off) inc += v;
    }
    __shared__ int wsum[8], wpre[8], nvsh;
    if (lane == 31) wsum[wid] = inc;
    __syncthreads();
    if (tid == 0) {
        int acc = 0;
        #pragma unroll
        for (int i = 0; i < 8; i++) { wpre[i] = acc; acc += wsum[i]; }
        nv[b] = acc; nvsh = acc;
    }
    __syncthreads();

    int ex = wpre[wid] + inc - s;
    int* rk = rank + b * Tc;
    #pragma unroll
    for (int j = 0; j < 8; j++) {
        rk[tid*8 + j] = loc[j] ? ex : -1;
        ex += loc[j];
    }

    const int NV = nvsh;
    __half* mo = mbc + b * Tc;
    for (int p = tid; p < Tc; p += 256)
        mo[p] = __ushort_as_half(p < NV ? (unsigned short)0x0000
                                        : (unsigned short)0xFC00);
}

// ---------------------------------------------------------------------------
// fp16 GEMM, 3-stage cp.async pipeline; 3 CTAs/SM (R13, proven).
// ---------------------------------------------------------------------------
#define HAS 40
#define G_STAGE_H (128*HAS)
#define G_SMEM_BYTES (2 * 3 * G_STAGE_H * 2)  // 61440

struct QKVJobs {
    const __half* A[3];
    const __half* W[3];
    const float* bias[3];
    __half* C[3];
};

template<int MODE>
__global__ __launch_bounds__(256, 3)
void gemm_h_kernel(QKVJobs P, const __half* Ao, const __half* Wo,
                   const float* biaso, float* Co, const int* __restrict__ nvArr)
{
    extern __shared__ __half gsm[];
    __half* sA = gsm;
    __half* sW = gsm + 3*G_STAGE_H;

    const int z = (MODE == 1) ? blockIdx.z : 0;
    const int bm = blockIdx.y * 128;
    const int bn = blockIdx.x * 128;

    if (MODE == 1 && z != 0) {
        if ((bm & 2047) >= nvArr[bm >> 11]) return;
    }

    const __half* A  = (MODE == 1) ? P.A[z] : Ao;
    const __half* W  = (MODE == 1) ? P.W[z] : Wo;
    const float* bias = (MODE == 1) ? P.bias[z] : biaso;
    const float scale = (MODE == 1 && z == 0) ? 0.125f * LOG2E : 1.0f;

    const int tid  = threadIdx.x;
    const int lane = tid & 31;
    const int w    = tid >> 5;
    const int g    = lane >> 2;
    const int t    = lane & 3;
    const int wm   = w & 3;
    const int wn   = w >> 2;

    const uint32_t sAb = smem_u32(sA);
    const uint32_t sWb = smem_u32(sW);

    auto issue = [&](int i) {
        const int buf = i % 3;
        const int k0 = i * 32;
        #pragma unroll
        for (int it = 0; it < 2; it++) {
            const int e = tid + it * 256;
            const int r = e >> 2, s = e & 3;
            cp_async16(sAb + (buf*G_STAGE_H + r*HAS + s*8)*2,
                       A + (size_t)(bm + r) * Kdim + k0 + s*8);
            cp_async16(sWb + (buf*G_STAGE_H + r*HAS + s*8)*2,
                       W + (size_t)(bn + r) * Kdim + k0 + s*8);
        }
    };

    float acc[2][8][4];
    #pragma unroll
    for (int mt = 0; mt < 2; mt++)
        #pragma unroll
        for (int nt = 0; nt < 8; nt++)
            #pragma unroll
            for (int j = 0; j < 4; j++) acc[mt][nt][j] = 0.f;

    issue(0); cp_commit();
    issue(1); cp_commit();

    const int NIT = Kdim / 32;   // 16
    for (int i = 0; i < NIT; i++) {
        const int buf = i % 3;
        if (i + 1 < NIT) asm volatile("cp.async.wait_group 1;");
        else             asm volatile("cp.async.wait_group 0;");
        __syncthreads();

        const uint32_t Ab = sAb + (buf*G_STAGE_H)*2;
        const uint32_t Wb = sWb + (buf*G_STAGE_H)*2;

        #pragma unroll
        for (int kt = 0; kt < 2; kt++) {
            uint32_t a[2][4];
            #pragma unroll
            for (int mt = 0; mt < 2; mt++) {
                const int row = wm*32 + mt*16 + (lane & 15);
                const int col = kt*16 + (lane >> 4) * 8;
                ldm_x4(a[mt][0], a[mt][1], a[mt][2], a[mt][3],
                       Ab + (row*HAS + col)*2);
            }
            #pragma unroll
            for (int nt = 0; nt < 8; nt++) {
                const int row = wn*64 + nt*8 + (lane & 7);
                const int col = kt*16 + ((lane >> 3) & 1) * 8;
                uint32_t b0, b1;
                ldm_x2(b0, b1, Wb + (row*HAS + col)*2);
                mma_f16(acc[0][nt], a[0][0], a[0][1], a[0][2], a[0][3], b0, b1);
                mma_f16(acc[1][nt], a[1][0], a[1][1], a[1][2], a[1][3], b0, b1);
            }
        }
        if (i + 2 < NIT) { issue(i + 2); cp_commit(); }
    }

    if (MODE == 0) {
        #pragma unroll
        for (int nt = 0; nt < 8; nt++) {
            const int col = bn + wn*64 + nt*8 + 2*t;
            const float2 bb = *(const float2*)(bias + col);
            #pragma unroll
            for (int mt = 0; mt < 2; mt++) {
                const int row0 = bm + wm*32 + mt*16 + g;
                const int row1 = row0 + 8;
                float2 v0, v1;
                v0.x = acc[mt][nt][0] + bb.x; v0.y = acc[mt][nt][1] + bb.y;
                v1.x = acc[mt][nt][2] + bb.x; v1.y = acc[mt][nt][3] + bb.y;
                *(float2*)(Co + (size_t)row0 * Ndim + col) = v0;
                *(float2*)(Co + (size_t)row1 * Ndim + col) = v1;
            }
        }
    } else {
        #pragma unroll
        for (int mt = 0; mt < 2; mt++) {
            const int row0 = bm + wm*32 + mt*16 + g;
            const int row1 = row0 + 8;
            const int b0_ = row0 >> 11, t0_ = row0 & 2047;
            const int b1_ = row1 >> 11, t1_ = row1 & 2047;
            #pragma unroll
            for (int nt = 0; nt < 8; nt++) {
                const int col = bn + wn*64 + nt*8 + 2*t;
                const float2 bb = *(const float2*)(bias + col);
                const int h  = col >> 6;
                const int dk = col & 63;
                float2 v0, v1;
                v0.x = (acc[mt][nt][0] + bb.x) * scale;
                v0.y = (acc[mt][nt][1] + bb.y) * scale;
                v1.x = (acc[mt][nt][2] + bb.x) * scale;
                v1.y = (acc[mt][nt][3] + bb.y) * scale;
                *(__half2*)(P.C[z] + ((((size_t)b0_*Hc + h)*Tc + t0_) * DKc) + dk)
                    = __float22half2_rn(v0);
                *(__half2*)(P.C[z] + ((((size_t)b1_*Hc + h)*Tc + t1_) * DKc) + dk)
                    = __float22half2_rn(v1);
            }
        }
    }
}

// ---------------------------------------------------------------------------
// Flash attention over COMPACTED keys; now 3 CTAs/SM (reg-capped), ph reuses
// dh in place (exp overwrites biased scores) to cut register liveness.
// ---------------------------------------------------------------------------
#define HS 72
#define SQ_OFF 0
#define SK_OFF (128*HS)
#define SV_OFF (SK_OFF + 3*64*HS)
#define AT_HALVES (SV_OFF + 3*64*HS)
#define AT_SMEM_BYTES (AT_HALVES * 2)   // 73728

__global__ __launch_bounds__(256, 3)
void attn_kernel(const __half* __restrict__ Q, const __half* __restrict__ K,
                 const __half* __restrict__ V, const __half* __restrict__ maskb,
                 const int* __restrict__ nv, __half* __restrict__ CTX)
{
    extern __shared__ __half hsm[];
    __half* sQ = hsm + SQ_OFF;
    __half* sK = hsm + SK_OFF;
    __half* sV = hsm + SV_OFF;
    __shared__ __half sMBh[3][64];

    const uint32_t sQb = smem_u32(sQ);
    const uint32_t sKb = smem_u32(sK);
    const uint32_t sVb = smem_u32(sV);
    const uint32_t sMBb = smem_u32(&sMBh[0][0]);
    const uint32_t* sMB32 = (const uint32_t*)&sMBh[0][0];

    const int tid  = threadIdx.x;
    const int lane = tid & 31;
    const int w    = tid >> 5;
    const int g    = lane >> 2;
    const int t    = lane & 3;
    const int r0   = w * 16;
    const int qt = blockIdx.x;
    const int h  = blockIdx.y;
    const int b  = blockIdx.z;

    const int NV = nv[b];
    const int NC = (NV + 63) >> 6;

    const size_t head_base = (((size_t)b * Hc + h) * Tc) * DKc;
    const __half* Qb = Q + head_base + (size_t)qt * 128 * DKc;
    const __half* Kb = K + head_base;
    const __half* Vb = V + head_base;
    const __half* MBp = maskb + b * Tc;

    const int l15 = lane & 15;
    const int lhi = lane >> 4;
    const int l7  = lane & 7;
    const int lb8 = (lane >> 3) & 1;
    const uint32_t aQaddr = sQb + ((r0 + l15)*HS + lhi*8)*2;
    const uint32_t bKoff = ((l7 + lhi*8)*HS + lb8*8)*2;
    const uint32_t bVoff = (l15*HS + lhi*8)*2;

    for (int idx = tid; idx < 3*64; idx += 256) {
        uint4 v; v.x = 0x00003C00u; v.y = 0; v.z = 0; v.w = 0;
        *(uint4*)(sV + idx*HS + 64) = v;
    }

    #pragma unroll
    for (int it = 0; it < 4; it++) {
        const int e = tid + it * 256;
        const int r = e >> 3, s = e & 7;
        cp_async16(sQb + (r*HS + s*8)*2, Qb + r*DKc + s*8);
    }

    auto issue_chunk = [&](int kc) {
        const int buf = kc % 3;
        const __half* Kc = Kb + (size_t)kc * 64 * DKc;
        const __half* Vc = Vb + (size_t)kc * 64 * DKc;
        #pragma unroll
        for (int it = 0; it < 2; it++) {
            const int e = tid + it * 256;
            const int r = e >> 3, s = e & 7;
            cp_async16(sKb + ((buf*64 + r)*HS + s*8)*2, Kc + r*DKc + s*8);
            cp_async16(sVb + ((buf*64 + r)*HS + s*8)*2, Vc + r*DKc + s*8);
        }
        if (tid < 8) cp_async16(sMBb + (buf*64 + tid*8)*2, MBp + kc*64 + tid*8);
    };

    if (NC > 0) issue_chunk(0);
    cp_commit();
    if (NC > 1) { issue_chunk(1); cp_commit(); }

    float of[8][4];
    float ofs[4];
    float mi0 = -1e30f, mi1 = -1e30f;
    #pragma unroll
    for (int nt = 0; nt < 8; nt++)
        #pragma unroll
        for (int j = 0; j < 4; j++) of[nt][j] = 0.f;
    ofs[0] = ofs[1] = ofs[2] = ofs[3] = 0.f;

    for (int kc = 0; kc < NC; kc++) {
        const int buf = kc % 3;
        if (kc + 1 < NC) asm volatile("cp.async.wait_group 1;");
        else             asm volatile("cp.async.wait_group 0;");
        __syncthreads();

        const uint32_t Kbuf = sKb + (buf*64*HS)*2;
        const uint32_t Vbuf = sVb + (buf*64*HS)*2;

        float sf[8][4];
        #pragma unroll
        for (int nt = 0; nt < 8; nt++)
            #pragma unroll
            for (int j = 0; j < 4; j++) sf[nt][j] = 0.f;

        #pragma unroll
        for (int kt = 0; kt < 4; kt++) {
            uint32_t a0, a1, a2, a3;
            ldm_x4(a0, a1, a2, a3, aQaddr + kt*32);
            #pragma unroll
            for (int nt = 0; nt < 8; nt += 2) {
                uint32_t b0, b1, b2, b3;
                ldm_x4(b0, b1, b2, b3, Kbuf + (nt*8*HS)*2 + kt*32 + bKoff);
                mma_f16(sf[nt],   a0, a1, a2, a3, b0, b1);
                mma_f16(sf[nt+1], a0, a1, a2, a3, b2, b3);
            }
        }

        // biased scores in packed fp16 (dh); later overwritten in place by exp
        uint32_t dh[8][2];
        #pragma unroll
        for (int nt = 0; nt < 8; nt++) {
            const uint32_t mb2 = sMB32[buf*32 + nt*4 + t];
            dh[nt][0] = add_h2u(cvt_h2(sf[nt][0], sf[nt][1]), mb2);
            dh[nt][1] = add_h2u(cvt_h2(sf[nt][2], sf[nt][3]), mb2);
        }
        uint32_t m0 = dh[0][0], m1 = dh[0][1];
        #pragma unroll
        for (int nt = 1; nt < 8; nt++) {
            m0 = max_h2u(m0, dh[nt][0]);
            m1 = max_h2u(m1, dh[nt][1]);
        }
        m0 = max_h2u(m0, prmtu(m0, m0, 0x1032));
        m1 = max_h2u(m1, prmtu(m1, m1, 0x1032));
        uint32_t mx2 = prmtu(m0, m1, 0x5410);
        mx2 = max_h2u(mx2, __shfl_xor_sync(0xffffffffu, mx2, 1));
        mx2 = max_h2u(mx2, __shfl_xor_sync(0xffffffffu, mx2, 2));
        const __half2 mxh = *(const __half2*)&mx2;
        const float mx0 = __low2float(mxh);
        const float mx1 = __high2float(mxh);

        const bool skiprow = (mx0 <= mi0) && (mx1 <= mi1) &&
                             (mi0 >= -60.f) && (mi1 >= -60.f);
        float mn0, mn1;
        if (__all_sync(0xffffffffu, skiprow)) {
            mn0 = mi0; mn1 = mi1;
        } else {
            mn0 = fmaxf(fmaxf(mi0, mx0), -60.f);
            mn1 = fmaxf(fmaxf(mi1, mx1), -60.f);
            const float al0 = ex2(mi0 - mn0);
            const float al1 = ex2(mi1 - mn1);
            mi0 = mn0; mi1 = mn1;
            #pragma unroll
            for (int nt = 0; nt < 8; nt++) {
                of[nt][0] *= al0; of[nt][1] *= al0;
                of[nt][2] *= al1; of[nt][3] *= al1;
            }
            ofs[0] *= al0; ofs[1] *= al0;
            ofs[2] *= al1; ofs[3] *= al1;
        }

        // p = exp2(d - mn) IN PLACE (dh becomes the PV A-fragments)
        __half2 mh0 = __float2half2_rn(mn0);
        __half2 mh1 = __float2half2_rn(mn1);
        const uint32_t mn0h2 = *(uint32_t*)&mh0;
        const uint32_t mn1h2 = *(uint32_t*)&mh1;
        #pragma unroll
        for (int nt = 0; nt < 8; nt++) {
            dh[nt][0] = ex2_h2u(sub_h2u(dh[nt][0], mn0h2));
            dh[nt][1] = ex2_h2u(sub_h2u(dh[nt][1], mn1h2));
        }

        #pragma unroll
        for (int kt = 0; kt < 4; kt++) {
            const uint32_t a0 = dh[2*kt][0];
            const uint32_t a1 = dh[2*kt][1];
            const uint32_t a2 = dh[2*kt+1][0];
            const uint32_t a3 = dh[2*kt+1][1];
            #pragma unroll
            for (int nt = 0; nt < 8; nt += 2) {
                uint32_t b0, b1, b2, b3;
                ldm_x4t(b0, b1, b2, b3, Vbuf + (kt*16*HS + nt*8)*2 + bVoff);
                mma_f16(of[nt],   a0, a1, a2, a3, b0, b1);
                mma_f16(of[nt+1], a0, a1, a2, a3, b2, b3);
            }
            uint32_t s0, s1;
            ldm_x2t(s0, s1, Vbuf + ((kt*16 + l15)*HS + 64)*2);
            mma_f16(ofs, a0, a1, a2, a3, s0, s1);
        }

        if (kc + 2 < NC) { issue_chunk(kc + 2); cp_commit(); }
    }
    if (NC == 0) asm volatile("cp.async.wait_group 0;");

    const float li0 = __shfl_sync(0xffffffffu, ofs[0], lane & 28);
    const float li1 = __shfl_sync(0xffffffffu, ofs[2], lane & 28);
    const float inv0 = (li0 > 0.f) ? (1.0f / li0) : 0.f;
    const float inv1 = (li1 > 0.f) ? (1.0f / li1) : 0.f;
    const int t0 = qt*128 + r0 + g;
    const int t1 = t0 + 8;
    #pragma unroll
    for (int nt = 0; nt < 8; nt++) {
        const int dk = nt*8 + 2*t;
        __half2 w0 = __float22half2_rn(make_float2(of[nt][0] * inv0, of[nt][1] * inv0));
        __half2 w1 = __float22half2_rn(make_float2(of[nt][2] * inv1, of[nt][3] * inv1));
        *(__half2*)(CTX + ((size_t)b * Tc + t0) * Fc + h*DKc + dk) = w0;
        *(__half2*)(CTX + ((size_t)b * Tc + t1) * Fc + h*DKc + dk) = w1;
    }
}

// ---------------------------------------------------------------------------
// Launcher
// ---------------------------------------------------------------------------
extern "C" void kernel_launch(void* const* d_in, const int* in_sizes, int n_in,
                              void* d_out, int out_size)
{
    const float* query = (const float*)d_in[0];
    const float* key   = (const float*)d_in[1];
    const float* value = (const float*)d_in[2];
    const int*   amask = (const int*)  d_in[3];
    const float* Wq = (const float*)d_in[4];
    const float* bq = (const float*)d_in[5];
    const float* Wk = (const float*)d_in[6];
    const float* bk = (const float*)d_in[7];
    const float* Wv = (const float*)d_in[8];
    const float* bv = (const float*)d_in[9];
    const float* Wo = (const float*)d_in[10];
    const float* bo = (const float*)d_in[11];
    float* out = (float*)d_out;

    __half *pXh, *pWh, *pQ, *pK, *pV, *pCTX, *pMB;
    int *pRK, *pNV;
    cudaGetSymbolAddress((void**)&pXh, g_Xh);
    cudaGetSymbolAddress((void**)&pWh, g_Wh);
    cudaGetSymbolAddress((void**)&pQ,  g_Qh);
    cudaGetSymbolAddress((void**)&pK,  g_Kh);
    cudaGetSymbolAddress((void**)&pV,  g_Vh);
    cudaGetSymbolAddress((void**)&pCTX, g_CTXh);
    cudaGetSymbolAddress((void**)&pMB, g_MBh);
    cudaGetSymbolAddress((void**)&pRK, g_RK);
    cudaGetSymbolAddress((void**)&pNV, g_NV);

    __half* xh[3] = { pXh, pXh + (size_t)Mdim*Fc, pXh + 2*(size_t)Mdim*Fc };
    __half* wh[4] = { pWh, pWh + (size_t)Fc*Fc, pWh + 2*(size_t)Fc*Fc, pWh + 3*(size_t)Fc*Fc };

    cudaFuncSetAttribute(attn_kernel,
                         cudaFuncAttributeMaxDynamicSharedMemorySize, AT_SMEM_BYTES);
    cudaFuncSetAttribute(gemm_h_kernel<0>,
                         cudaFuncAttributeMaxDynamicSharedMemorySize, G_SMEM_BYTES);
    cudaFuncSetAttribute(gemm_h_kernel<1>,
                         cudaFuncAttributeMaxDynamicSharedMemorySize, G_SMEM_BYTES);

    // 1) mask compaction first (cvt gathers key/value rows by rank)
    compact_mask_kernel<<<Bc, 256>>>(amask, pRK, pMB, pNV);

    const int NB_IN = (Mdim*Fc)/(256*4);   // 4096
    const int NB_W  = (Fc*Fc)/(256*4);     // 256
    CvtJobs7 J;
    J.src[0] = query; J.src[1] = key; J.src[2] = value;
    J.src[3] = Wq; J.src[4] = Wk; J.src[5] = Wv; J.src[6] = Wo;
    J.dst[0] = xh[0]; J.dst[1] = xh[1]; J.dst[2] = xh[2];
    J.dst[3] = wh[0]; J.dst[4] = wh[1]; J.dst[5] = wh[2]; J.dst[6] = wh[3];
    J.nblk[0] = NB_IN; J.nblk[1] = NB_IN; J.nblk[2] = NB_IN;
    J.nblk[3] = NB_W;  J.nblk[4] = NB_W;  J.nblk[5] = NB_W;  J.nblk[6] = NB_W;
    cvt_kernel<<<dim3(NB_IN, 7), 256>>>(J, pRK);

    // 2) fused QKV projections; K/V over compacted inputs, dead blocks skipped
    QKVJobs P;
    P.A[0] = xh[0]; P.A[1] = xh[1]; P.A[2] = xh[2];
    P.W[0] = wh[0]; P.W[1] = wh[1]; P.W[2] = wh[2];
    P.bias[0] = bq; P.bias[1] = bk; P.bias[2] = bv;
    P.C[0] = pQ;    P.C[1] = pK;   P.C[2] = pV;
    gemm_h_kernel<1><<<dim3(Ndim/128, Mdim/128, 3), 256, G_SMEM_BYTES>>>(
        P, nullptr, nullptr, nullptr, nullptr, pNV);

    // 3) attention over compacted keys (3 CTAs/SM)
    attn_kernel<<<dim3(Tc/128, Hc, Bc), 256, AT_SMEM_BYTES>>>(pQ, pK, pV, pMB, pNV, pCTX);

    // 4) output projection
    QKVJobs PD = {};
    gemm_h_kernel<0><<<dim3(Ndim/128, Mdim/128), 256, G_SMEM_BYTES>>>(
        PD, pCTX, wh[3], bo, out, nullptr);
}